// round 11
// baseline (speedup 1.0000x reference)
#include <cuda_runtime.h>
#include <cuda_fp16.h>
#include <cstdint>

#define BB 64
#define SS 196
#define HALFS 98
#define OO 10
#define ESLAB_U2 2048          // uint2 per E-slab (32 x 64)
#define ESLAB_B 16384          // bytes per E-slab
#define RING 6
#define NT 160                 // 4 worker warps + 1 TMA warp

// E = C - I in fp16: [slab k][mm 0..31][n 0..63] uint2 = {half2(E0,E1)@m=2mm, @m=2mm+1}
__device__ __align__(128) uint2 g_EhL[HALFS * ESLAB_U2];
__device__ __align__(128) uint2 g_EhR[HALFS * ESLAB_U2];   // transposed, chain order
__device__ float g_vecL[BB][64];
__device__ float g_vecR[BB][64];

typedef unsigned long long ull;

// ---------------------------------------------------------------------------
__device__ __forceinline__ uint32_t smem_u32(const void* p) {
    uint32_t a;
    asm("{ .reg .u64 t; cvta.to.shared.u64 t, %1; cvt.u32.u64 %0, t; }"
        : "=r"(a) : "l"(p));
    return a;
}
__device__ __forceinline__ void mbar_init(uint32_t a, uint32_t cnt) {
    asm volatile("mbarrier.init.shared.b64 [%0], %1;" :: "r"(a), "r"(cnt) : "memory");
}
__device__ __forceinline__ void mbar_expect_tx(uint32_t a, uint32_t bytes) {
    asm volatile("mbarrier.arrive.expect_tx.shared.b64 _, [%0], %1;"
                 :: "r"(a), "r"(bytes) : "memory");
}
__device__ __forceinline__ void mbar_wait(uint32_t a, uint32_t phase) {
    asm volatile(
        "{\n\t.reg .pred P;\n\t"
        "W_%=:\n\t"
        "mbarrier.try_wait.parity.shared.b64 P, [%0], %1;\n\t"
        "@!P bra W_%=;\n\t}"
        :: "r"(a), "r"(phase) : "memory");
}
__device__ __forceinline__ void bulk_g2s(uint32_t dst, const void* src,
                                         uint32_t bytes, uint32_t mbar) {
    asm volatile(
        "cp.async.bulk.shared::cluster.global.mbarrier::complete_tx::bytes "
        "[%0], [%1], %2, [%3];"
        :: "r"(dst), "l"(src), "r"(bytes), "r"(mbar) : "memory");
}

// packed f32x2 helpers
#define FMA_F32X2(d, a, b, c) \
    asm("fma.rn.f32x2 %0, %1, %2, %3;" : "=l"(d) : "l"(a), "l"(b), "l"(c))
#define ADD_F32X2(d, a, b) \
    asm("add.rn.f32x2 %0, %1, %2;" : "=l"(d) : "l"(a), "l"(b))
#define UNPACK_F32X2(lo, hi, in) \
    asm("mov.b64 {%0, %1}, %2;" : "=f"(lo), "=f"(hi) : "l"(in))

// half2 -> packed f32x2 (one 64-bit reg)
__device__ __forceinline__ ull h2_to_f32x2(uint32_t h) {
    ull r;
    asm("{ .reg .b16 a, b; .reg .f32 lo, hi;\n\t"
        "mov.b32 {a, b}, %1;\n\t"
        "cvt.f32.f16 lo, a;\n\t"
        "cvt.f32.f16 hi, b;\n\t"
        "mov.b64 %0, {lo, hi}; }"
        : "=l"(r) : "r"(h));
    return r;
}

// ---------------------------------------------------------------------------
// Kernel 1: prep. Builds EhL (left, raw orientation) and EhR (right,
// transposed, chain order k -> original slab s = 195-k). E = C - I, fp16.
// ---------------------------------------------------------------------------
__global__ __launch_bounds__(256) void prep_kernel(const float* __restrict__ cores)
{
    const int bid = blockIdx.x;
    const int t = threadIdx.x;

    if (bid < HALFS) {
        const float2* c2 = (const float2*)cores + (size_t)bid * 4096;
        uint2* dst = g_EhL + (size_t)bid * ESLAB_U2;
#pragma unroll
        for (int i = 0; i < 8; i++) {
            int idx = t + i * 256;
            int mm = idx >> 6, n = idx & 63;
            float2 a = c2[(2 * mm) * 64 + n];
            float2 b = c2[(2 * mm + 1) * 64 + n];
            if (2 * mm == n)     { a.x -= 1.f; a.y -= 1.f; }
            if (2 * mm + 1 == n) { b.x -= 1.f; b.y -= 1.f; }
            __half2 ha = __float22half2_rn(a);
            __half2 hb = __float22half2_rn(b);
            uint32_t ua, ub;
            memcpy(&ua, &ha, 4); memcpy(&ub, &hb, 4);
            dst[idx] = make_uint2(ua, ub);
        }
    } else {
        const int k = bid - HALFS;
        const int s = SS - 1 - k;
        const float4* c4 = (const float4*)cores + (size_t)s * 2048;
        uint2* dst = g_EhR + (size_t)k * ESLAB_U2;
#pragma unroll
        for (int i = 0; i < 8; i++) {
            int idx = t + i * 256;
            int mm = idx >> 6, n = idx & 63;
            float4 f = c4[n * 32 + mm];      // (C0,C1)@(n,2mm), (C0,C1)@(n,2mm+1)
            float2 a = make_float2(f.x, f.y);
            float2 b = make_float2(f.z, f.w);
            if (2 * mm == n)     { a.x -= 1.f; a.y -= 1.f; }
            if (2 * mm + 1 == n) { b.x -= 1.f; b.y -= 1.f; }
            __half2 ha = __float22half2_rn(a);
            __half2 hb = __float22half2_rn(b);
            uint32_t ua, ub;
            memcpy(&ua, &ha, 4); memcpy(&ub, &hb, 4);
            dst[idx] = make_uint2(ua, ub);
        }
    }
}

// ---------------------------------------------------------------------------
// Kernel 2: 64 CTAs x 160 threads (4 worker warps + 1 TMA warp).
// Warp w, lane (g = m-half, c): column n = w*16 + c.
// E slabs (16KB) ring through SMEM via TMA; converted to packed f32x2 regs
// at prefetch time (double-buffered, shared by both batches).
// lv stored duplicated (v,v) so ulonglong2 LDS.128 feeds fma.rn.f32x2 directly.
// new_lv[n] = (x0+x1)*lv[n] + x0*(lv.E0)[n] + x1*(lv.E1)[n].
// ---------------------------------------------------------------------------
__global__ __launch_bounds__(NT, 1) void chain_kernel(const float* __restrict__ x)
{
    extern __shared__ __align__(128) unsigned char dynsm[];
    uint2*  ringE = (uint2*)dynsm;                                  // 6 x 16KB
    float2* lvd   = (float2*)(dynsm + RING * ESLAB_B);              // [b][buf][64] dup
    float2* xsh   = (float2*)(dynsm + RING * ESLAB_B + 2048);       // [2][98]
    uint64_t* mbp = (uint64_t*)(dynsm + RING * ESLAB_B + 2048 + 1568);

    const uint32_t fb = smem_u32(mbp);
    const uint32_t ru = smem_u32(dynsm);

    const int t    = threadIdx.x;
    const int w    = t >> 5;
    const int lane = t & 31;
    const int g    = lane >> 4;
    const int c    = lane & 15;
    const int half = blockIdx.x >> 5;
    const int b0   = (blockIdx.x & 31) * 2;

    const uint2* srcE = half ? g_EhR : g_EhL;

    // stage x in iteration order
    const float2* xf = (const float2*)x;        // [B][S]
    for (int k = t; k < HALFS; k += NT) {
        int s = half ? (SS - 1 - k) : k;
        xsh[k]         = xf[(b0 + 0) * SS + s];
        xsh[HALFS + k] = xf[(b0 + 1) * SS + s];
    }
    // init lv buf0 both batches, duplicated
    if (t < 64) {
        float v = (t == 0) ? 1.f : 0.f;
        lvd[0 * 64 + t] = make_float2(v, v);    // b0 buf0
        lvd[2 * 64 + t] = make_float2(v, v);    // b1 buf0
    }
    if (t == 0)
        for (int j = 0; j < RING; j++) mbar_init(fb + 8 * j, 1);
    __syncthreads();

    if (w == 4 && lane == 0) {                  // prologue: slabs 0..5
        for (int s = 0; s < RING; s++) {
            mbar_expect_tx(fb + 8 * s, ESLAB_B);
            bulk_g2s(ru + s * ESLAB_B, srcE + (size_t)s * ESLAB_U2,
                     ESLAB_B, fb + 8 * s);
        }
        mbar_wait(fb + 0, 0);                   // slab 0 (reg load)
        mbar_wait(fb + 8, 0);                   // slab 1 (step-0 prefetch)
    }
    __syncthreads();

    if (w < 4) {
        // ============================ workers ============================
        const int n = w * 16 + c;
        const int eoff = g * 1024 + n;          // uint2 offset of (mm = g*16, n)
        const bool wr = (g == 0);

        ull efA[32], efB[32];
        {
            const uint2* P = ringE + eoff;
#pragma unroll
            for (int j = 0; j < 16; j++) {
                uint2 e = P[j * 64];
                efA[2 * j]     = h2_to_f32x2(e.x);
                efA[2 * j + 1] = h2_to_f32x2(e.y);
            }
        }
        int slotn = 1;                          // ring slot of slab k+1

#define WSTEP(EF, EFN, K, PAR)                                               \
        {                                                                    \
            /* ---------- batch 0 ---------- */                              \
            {                                                                \
                const ulonglong2* lv2 =                                      \
                    (const ulonglong2*)(lvd + ((PAR)) * 64 + g * 32);        \
                ull aca = 0ull, acb = 0ull;                                  \
                _Pragma("unroll")                                            \
                for (int j = 0; j < 16; j++) {                               \
                    ulonglong2 L = lv2[j];                                   \
                    FMA_F32X2(aca, L.x, EF[2 * j], aca);                     \
                    FMA_F32X2(acb, L.y, EF[2 * j + 1], acb);                 \
                }                                                            \
                ull acc; ADD_F32X2(acc, aca, acb);                           \
                float Sx, Sy; UNPACK_F32X2(Sx, Sy, acc);                     \
                float2 xk = xsh[(K)];                                        \
                float part = fmaf(xk.x, Sx, xk.y * Sy);                      \
                float oth = __shfl_xor_sync(0xffffffffu, part, 16);          \
                if (wr) {                                                    \
                    float lvold = lvd[(PAR) * 64 + n].x;                     \
                    float nv = fmaf(xk.x + xk.y, lvold, part + oth);         \
                    lvd[((PAR) ^ 1) * 64 + n] = make_float2(nv, nv);         \
                }                                                            \
            }                                                                \
            /* ---------- batch 1 ---------- */                              \
            {                                                                \
                const ulonglong2* lv2 =                                      \
                    (const ulonglong2*)(lvd + (2 + (PAR)) * 64 + g * 32);    \
                ull aca = 0ull, acb = 0ull;                                  \
                _Pragma("unroll")                                            \
                for (int j = 0; j < 16; j++) {                               \
                    ulonglong2 L = lv2[j];                                   \
                    FMA_F32X2(aca, L.x, EF[2 * j], aca);                     \
                    FMA_F32X2(acb, L.y, EF[2 * j + 1], acb);                 \
                }                                                            \
                ull acc; ADD_F32X2(acc, aca, acb);                           \
                float Sx, Sy; UNPACK_F32X2(Sx, Sy, acc);                     \
                float2 xk = xsh[HALFS + (K)];                                \
                float part = fmaf(xk.x, Sx, xk.y * Sy);                      \
                float oth = __shfl_xor_sync(0xffffffffu, part, 16);          \
                if (wr) {                                                    \
                    float lvold = lvd[(2 + (PAR)) * 64 + n].x;               \
                    float nv = fmaf(xk.x + xk.y, lvold, part + oth);         \
                    lvd[(2 + ((PAR) ^ 1)) * 64 + n] = make_float2(nv, nv);   \
                }                                                            \
            }                                                                \
            /* ---------- prefetch + convert slab K+1 (after STS) -------- */\
            if ((K) < HALFS - 1) {                                           \
                const uint2* Ns = ringE + slotn * ESLAB_U2 + eoff;           \
                _Pragma("unroll")                                            \
                for (int j = 0; j < 16; j++) {                               \
                    uint2 e = Ns[j * 64];                                    \
                    EFN[2 * j]     = h2_to_f32x2(e.x);                       \
                    EFN[2 * j + 1] = h2_to_f32x2(e.y);                       \
                }                                                            \
            }                                                                \
            slotn = (slotn == RING - 1) ? 0 : slotn + 1;                     \
            __syncthreads();                                                 \
        }

#pragma unroll 1
        for (int k = 0; k < HALFS; k += 2) {
            WSTEP(efA, efB, k, 0);
            WSTEP(efB, efA, k + 1, 1);
        }
#undef WSTEP

        if (t < 64) {        // final lv in buffer 0 (98 even)
            float v0 = lvd[0 * 64 + t].x;
            float v1 = lvd[2 * 64 + t].x;
            if (half == 0) { g_vecL[b0][t] = v0; g_vecL[b0 + 1][t] = v1; }
            else           { g_vecR[b0][t] = v0; g_vecR[b0 + 1][t] = v1; }
        }
    } else {
        // ============================ TMA warp ============================
#pragma unroll 1
        for (int k = 0; k < HALFS; k++) {
            if (lane == 0 && k + 2 < HALFS)     // certify slab k+2
                mbar_wait(fb + 8 * ((k + 2) % RING), ((k + 2) / RING) & 1);
            __syncthreads();
            if (lane == 0 && k + RING < HALFS) {   // refill slot k%RING
                mbar_expect_tx(fb + 8 * (k % RING), ESLAB_B);
                bulk_g2s(ru + (k % RING) * ESLAB_B,
                         srcE + (size_t)(k + RING) * ESLAB_U2,
                         ESLAB_B, fb + 8 * (k % RING));
            }
        }
    }
}

// ---------------------------------------------------------------------------
// Kernel 3: 640 CTAs, CTA = (b, o): out[b,o] = sum_{l,r} L[b,l] oc[o,l,r] R[b,r]
// ---------------------------------------------------------------------------
__global__ __launch_bounds__(64) void out_kernel(const float* __restrict__ oc,
                                                 float* __restrict__ out)
{
    const int bo = blockIdx.x;
    const int b  = bo / OO;
    const int o  = bo - b * OO;
    const int r  = threadIdx.x;
    __shared__ float Ls[64];
    __shared__ float red[2];

    Ls[r] = g_vecL[b][r];
    const float R = g_vecR[b][r];
    __syncthreads();

    float acc = 0.f;
    const float* m = oc + o * 4096 + r;
#pragma unroll 16
    for (int l = 0; l < 64; l++) acc = fmaf(Ls[l], m[l * 64], acc);
    acc *= R;
#pragma unroll
    for (int off = 16; off; off >>= 1)
        acc += __shfl_down_sync(0xffffffffu, acc, off);
    if ((r & 31) == 0) red[r >> 5] = acc;
    __syncthreads();
    if (r == 0) out[b * OO + o] = red[0] + red[1];
}

// ---------------------------------------------------------------------------
extern "C" void kernel_launch(void* const* d_in, const int* in_sizes, int n_in,
                              void* d_out, int out_size)
{
    const float* x = nullptr;
    const float* cores = nullptr;
    const float* oc = nullptr;
    for (int i = 0; i < n_in; i++) {
        if (in_sizes[i] == BB * SS * 2)              x = (const float*)d_in[i];
        else if (in_sizes[i] == SS * 64 * 64 * 2)    cores = (const float*)d_in[i];
        else if (in_sizes[i] == OO * 64 * 64)        oc = (const float*)d_in[i];
    }

    const int DYN_SMEM = RING * ESLAB_B + 2048 + 1568 + 64;
    cudaFuncSetAttribute(chain_kernel, cudaFuncAttributeMaxDynamicSharedMemorySize, DYN_SMEM);

    prep_kernel<<<2 * HALFS, 256>>>(cores);
    chain_kernel<<<64, NT, DYN_SMEM>>>(x);
    out_kernel<<<BB * OO, 64>>>(oc, (float*)d_out);
}

// round 13
// speedup vs baseline: 1.1808x; 1.1808x over previous
#include <cuda_runtime.h>
#include <cuda_fp16.h>
#include <cstdint>

#define BB 64
#define SS 196
#define HALFS 98
#define OO 10
#define ESLAB_U2 2048          // uint2 per E-slab: [mm 0..31][n 0..63]
#define ESLAB_B 16384          // bytes per E-slab
#define RING 6
#define NT 160                 // 4 worker warps + 1 TMA warp

// E = C - I in fp16, chain-ordered. uint2 = {half2 @ m=2mm, half2 @ m=2mm+1}
__device__ __align__(128) uint2 g_EhL[HALFS * ESLAB_U2];
__device__ __align__(128) uint2 g_EhR[HALFS * ESLAB_U2];   // transposed
__device__ float g_vecL[BB][64];
__device__ float g_vecR[BB][64];

// ---------------------------------------------------------------------------
__device__ __forceinline__ uint32_t smem_u32(const void* p) {
    uint32_t a;
    asm("{ .reg .u64 t; cvta.to.shared.u64 t, %1; cvt.u32.u64 %0, t; }"
        : "=r"(a) : "l"(p));
    return a;
}
__device__ __forceinline__ void mbar_init(uint32_t a, uint32_t cnt) {
    asm volatile("mbarrier.init.shared.b64 [%0], %1;" :: "r"(a), "r"(cnt) : "memory");
}
__device__ __forceinline__ void mbar_expect_tx(uint32_t a, uint32_t bytes) {
    asm volatile("mbarrier.arrive.expect_tx.shared.b64 _, [%0], %1;"
                 :: "r"(a), "r"(bytes) : "memory");
}
__device__ __forceinline__ void mbar_wait(uint32_t a, uint32_t phase) {
    asm volatile(
        "{\n\t.reg .pred P;\n\t"
        "W_%=:\n\t"
        "mbarrier.try_wait.parity.shared.b64 P, [%0], %1;\n\t"
        "@!P bra W_%=;\n\t}"
        :: "r"(a), "r"(phase) : "memory");
}
__device__ __forceinline__ void bulk_g2s(uint32_t dst, const void* src,
                                         uint32_t bytes, uint32_t mbar) {
    asm volatile(
        "cp.async.bulk.shared::cluster.global.mbarrier::complete_tx::bytes "
        "[%0], [%1], %2, [%3];"
        :: "r"(dst), "l"(src), "r"(bytes), "r"(mbar) : "memory");
}

__device__ __forceinline__ uint32_t pack_e(float2 a) {
    __half2 h = __float22half2_rn(a);
    uint32_t u;
    memcpy(&u, &h, 4);
    return u;
}

// ---------------------------------------------------------------------------
// Kernel 1a: left prep (direct, coalesced). CTA = slab s.
// EhL[s][mm][n] = {h2(C[s][2mm][n]-I), h2(C[s][2mm+1][n]-I)}
// ---------------------------------------------------------------------------
__global__ __launch_bounds__(256) void prepL_kernel(const float* __restrict__ cores)
{
    const int s = blockIdx.x;
    const int t = threadIdx.x;
    const float2* c2 = (const float2*)cores + (size_t)s * 4096;
    uint2* dst = g_EhL + (size_t)s * ESLAB_U2;

#pragma unroll
    for (int i = 0; i < 8; i++) {
        int idx = t + i * 256;
        int mm = idx >> 6, n = idx & 63;
        float2 a = c2[(2 * mm) * 64 + n];
        float2 b = c2[(2 * mm + 1) * 64 + n];
        if (2 * mm == n)     { a.x -= 1.f; a.y -= 1.f; }
        if (2 * mm + 1 == n) { b.x -= 1.f; b.y -= 1.f; }
        dst[idx] = make_uint2(pack_e(a), pack_e(b));
    }
}

// ---------------------------------------------------------------------------
// Kernel 1b: right prep (transpose via SMEM tile). CTA = chain index k.
// EhR[k][mm][n] = {h2(C[195-k][n][2mm]-I), h2(C[195-k][n][2mm+1]-I)}
// Reads coalesced (m fastest), tile-transposes, writes coalesced (n fastest).
// ---------------------------------------------------------------------------
__global__ __launch_bounds__(256) void prepR_kernel(const float* __restrict__ cores)
{
    __shared__ uint2 tile[32][65];
    const int k = blockIdx.x;
    const int s = SS - 1 - k;
    // FIX vs R12: slab = 8192 floats = 2048 float4 (was erroneously 1024)
    const float4* c4 = (const float4*)cores + (size_t)s * 2048;  // [n][mm] float4
    uint2* dst = g_EhR + (size_t)k * ESLAB_U2;
    const int t = threadIdx.x;

#pragma unroll
    for (int i = 0; i < 8; i++) {
        int idx = t + i * 256;                 // mm fastest -> coalesced float4
        int n = idx >> 5, mm = idx & 31;
        float4 f = c4[idx];                    // C[n][2mm](i0,i1), C[n][2mm+1](i0,i1)
        float2 a = make_float2(f.x, f.y);
        float2 b = make_float2(f.z, f.w);
        if (2 * mm == n)     { a.x -= 1.f; a.y -= 1.f; }
        if (2 * mm + 1 == n) { b.x -= 1.f; b.y -= 1.f; }
        tile[mm][n] = make_uint2(pack_e(a), pack_e(b));
    }
    __syncthreads();
#pragma unroll
    for (int i = 0; i < 8; i++) {
        int idx = t + i * 256;                 // n fastest -> coalesced store
        int mm = idx >> 6, n = idx & 63;
        dst[idx] = tile[mm][n];
    }
}

// ---------------------------------------------------------------------------
// Kernel 2: 64 CTAs x 160 threads (4 worker warps + 1 TMA warp).
// R10 datapath (scalar fmaf, float2 A/B[32], lv 72-padded, shfl.bfly(16),
// one __syncthreads/step) with fp16-E staging: prefetch converts 16 uint2
// -> 32 float2 in the post-STS window. Identity term added exactly in fp32.
// ---------------------------------------------------------------------------
__global__ __launch_bounds__(NT, 1) void chain_kernel(const float* __restrict__ x)
{
    extern __shared__ __align__(128) unsigned char dynsm[];
    uint2*  ringE = (uint2*)dynsm;                                // 6 x 16KB
    float*  lvsm  = (float*)(dynsm + RING * ESLAB_B);             // lv0[2][72], lv1[2][72]
    float2* xsh   = (float2*)(dynsm + RING * ESLAB_B + 1152);     // [2][98]
    uint64_t* mbp = (uint64_t*)(dynsm + RING * ESLAB_B + 1152 + 1568);

    const uint32_t fb = smem_u32(mbp);
    const uint32_t ru = smem_u32(dynsm);

    const int t    = threadIdx.x;
    const int w    = t >> 5;
    const int lane = t & 31;
    const int g    = lane >> 4;
    const int half = blockIdx.x >> 5;
    const int b0   = (blockIdx.x & 31) * 2;

    const uint2* srcE = half ? g_EhR : g_EhL;     // both chain-ordered

    // stage x in iteration order
    const float2* xf = (const float2*)x;          // [B][S]
    for (int k = t; k < HALFS; k += NT) {
        int s = half ? (SS - 1 - k) : k;
        xsh[k]         = xf[(b0 + 0) * SS + s];
        xsh[HALFS + k] = xf[(b0 + 1) * SS + s];
    }
    // init lv buf0 (padded layout: half h at offset h*36)
    if (t < 64) {
        int h = t >> 5, p = t & 31;
        float v = (t == 0) ? 1.f : 0.f;
        lvsm[h * 36 + p]       = v;   // batch0, buf0
        lvsm[144 + h * 36 + p] = v;   // batch1, buf0
    }
    if (t == 0)
        for (int j = 0; j < RING; j++) mbar_init(fb + 8 * j, 1);
    __syncthreads();

    if (w == 4 && lane == 0) {            // prologue: slabs 0..5
        for (int s = 0; s < RING; s++) {
            mbar_expect_tx(fb + 8 * s, ESLAB_B);
            bulk_g2s(ru + s * ESLAB_B, srcE + (size_t)s * ESLAB_U2,
                     ESLAB_B, fb + 8 * s);
        }
        mbar_wait(fb + 0, 0);             // slab 0 (reg load)
        mbar_wait(fb + 8, 0);             // slab 1 (step-0 prefetch)
    }
    __syncthreads();

    if (w < 4) {
        // ============================ workers ============================
        const int c  = lane & 15;
        const int n  = w * 16 + c;
        const int eoff = g * 1024 + n;    // uint2 offset of (mm = g*16, n)
        const int hh = w >> 1;            // n >> 5
        const int sto = hh * 36 + (w & 1) * 16 + c;   // lv slot for column n
        const bool wr = (g == 0);

        float2 A[32], B[32];
        {
            const uint2* P = ringE + eoff;
#pragma unroll
            for (int j = 0; j < 16; j++) {
                uint2 e = P[j * 64];
                A[2 * j]     = __half22float2(*reinterpret_cast<const __half2*>(&e.x));
                A[2 * j + 1] = __half22float2(*reinterpret_cast<const __half2*>(&e.y));
            }
        }
        int slotn = 1;                    // ring slot of slab k+1

#define WSTEP(CUR, NXT, K, PAR)                                              \
        {                                                                    \
            /* ---------- batch 0: accumulate correction ---------- */       \
            float p0;                                                        \
            float2 xk0 = xsh[(K)];                                           \
            {                                                                \
                const float4* lv4 = (const float4*)(lvsm + (PAR) * 72 + g * 36); \
                float4 L[8];                                                 \
                _Pragma("unroll")                                            \
                for (int q = 0; q < 8; q++) L[q] = lv4[q];                   \
                float sx0 = 0.f, sx1 = 0.f, sy0 = 0.f, sy1 = 0.f;            \
                _Pragma("unroll")                                            \
                for (int q = 0; q < 8; q++) {                                \
                    float2 c0 = CUR[4*q+0], c1 = CUR[4*q+1];                 \
                    float2 c2 = CUR[4*q+2], c3 = CUR[4*q+3];                 \
                    sx0 = fmaf(L[q].x, c0.x, sx0); sy0 = fmaf(L[q].x, c0.y, sy0); \
                    sx1 = fmaf(L[q].y, c1.x, sx1); sy1 = fmaf(L[q].y, c1.y, sy1); \
                    sx0 = fmaf(L[q].z, c2.x, sx0); sy0 = fmaf(L[q].z, c2.y, sy0); \
                    sx1 = fmaf(L[q].w, c3.x, sx1); sy1 = fmaf(L[q].w, c3.y, sy1); \
                }                                                            \
                p0 = fmaf(xk0.x, sx0 + sx1, xk0.y * (sy0 + sy1));            \
            }                                                                \
            /* -------- batch 1 lv preload + identity lv_old reads ------- */\
            float4 M[8];                                                     \
            {                                                                \
                const float4* lv4 = (const float4*)(lvsm + 144 + (PAR) * 72 + g * 36); \
                _Pragma("unroll")                                            \
                for (int q = 0; q < 8; q++) M[q] = lv4[q];                   \
            }                                                                \
            float lvo0 = 0.f, lvo1 = 0.f;                                    \
            if (wr) {                                                        \
                lvo0 = lvsm[(PAR) * 72 + sto];                               \
                lvo1 = lvsm[144 + (PAR) * 72 + sto];                         \
            }                                                                \
            /* ---------- batch 0 tail ---------- */                         \
            {                                                                \
                float oth = __shfl_xor_sync(0xffffffffu, p0, 16);            \
                if (wr) lvsm[((PAR) ^ 1) * 72 + sto] =                       \
                    fmaf(xk0.x + xk0.y, lvo0, p0 + oth);                     \
            }                                                                \
            /* ---------- batch 1 ---------- */                              \
            {                                                                \
                float sx0 = 0.f, sx1 = 0.f, sy0 = 0.f, sy1 = 0.f;            \
                _Pragma("unroll")                                            \
                for (int q = 0; q < 8; q++) {                                \
                    float2 c0 = CUR[4*q+0], c1 = CUR[4*q+1];                 \
                    float2 c2 = CUR[4*q+2], c3 = CUR[4*q+3];                 \
                    sx0 = fmaf(M[q].x, c0.x, sx0); sy0 = fmaf(M[q].x, c0.y, sy0); \
                    sx1 = fmaf(M[q].y, c1.x, sx1); sy1 = fmaf(M[q].y, c1.y, sy1); \
                    sx0 = fmaf(M[q].z, c2.x, sx0); sy0 = fmaf(M[q].z, c2.y, sy0); \
                    sx1 = fmaf(M[q].w, c3.x, sx1); sy1 = fmaf(M[q].w, c3.y, sy1); \
                }                                                            \
                float2 xk = xsh[HALFS + (K)];                                \
                float p1 = fmaf(xk.x, sx0 + sx1, xk.y * (sy0 + sy1));        \
                float oth = __shfl_xor_sync(0xffffffffu, p1, 16);            \
                if (wr) lvsm[144 + ((PAR) ^ 1) * 72 + sto] =                 \
                    fmaf(xk.x + xk.y, lvo1, p1 + oth);                       \
            }                                                                \
            /* ------ prefetch+convert slab K+1 (post-STS skew window) --- */\
            if ((K) < HALFS - 1) {                                           \
                const uint2* Ns = ringE + slotn * ESLAB_U2 + eoff;           \
                _Pragma("unroll")                                            \
                for (int j = 0; j < 16; j++) {                               \
                    uint2 e = Ns[j * 64];                                    \
                    NXT[2 * j] =                                             \
                        __half22float2(*reinterpret_cast<const __half2*>(&e.x)); \
                    NXT[2 * j + 1] =                                         \
                        __half22float2(*reinterpret_cast<const __half2*>(&e.y)); \
                }                                                            \
            }                                                                \
            slotn = (slotn == RING - 1) ? 0 : slotn + 1;                     \
            __syncthreads();                                                 \
        }

#pragma unroll 1
        for (int k = 0; k < HALFS; k += 2) {
            WSTEP(A, B, k, 0);
            WSTEP(B, A, k + 1, 1);
        }
#undef WSTEP

        if (t < 64) {        // final lv in buffer 0 (98 even)
            int h = t >> 5, p = t & 31;
            float v0 = lvsm[h * 36 + p];
            float v1 = lvsm[144 + h * 36 + p];
            if (half == 0) { g_vecL[b0][t] = v0; g_vecL[b0 + 1][t] = v1; }
            else           { g_vecR[b0][t] = v0; g_vecR[b0 + 1][t] = v1; }
        }
    } else {
        // ============================ TMA warp ============================
#pragma unroll 1
        for (int k = 0; k < HALFS; k++) {
            if (lane == 0 && k + 2 < HALFS)     // certify slab k+2
                mbar_wait(fb + 8 * ((k + 2) % RING), ((k + 2) / RING) & 1);
            __syncthreads();
            if (lane == 0 && k + RING < HALFS) {   // refill slot k%RING
                mbar_expect_tx(fb + 8 * (k % RING), ESLAB_B);
                bulk_g2s(ru + (k % RING) * ESLAB_B,
                         srcE + (size_t)(k + RING) * ESLAB_U2,
                         ESLAB_B, fb + 8 * (k % RING));
            }
        }
    }
}

// ---------------------------------------------------------------------------
// Kernel 3: 640 CTAs, CTA = (b, o): out[b,o] = sum_{l,r} L[b,l] oc[o,l,r] R[b,r]
// ---------------------------------------------------------------------------
__global__ __launch_bounds__(64) void out_kernel(const float* __restrict__ oc,
                                                 float* __restrict__ out)
{
    const int bo = blockIdx.x;
    const int b  = bo / OO;
    const int o  = bo - b * OO;
    const int r  = threadIdx.x;
    __shared__ float Ls[64];
    __shared__ float red[2];

    Ls[r] = g_vecL[b][r];
    const float R = g_vecR[b][r];
    __syncthreads();

    float acc = 0.f;
    const float* m = oc + o * 4096 + r;
#pragma unroll 16
    for (int l = 0; l < 64; l++) acc = fmaf(Ls[l], m[l * 64], acc);
    acc *= R;
#pragma unroll
    for (int off = 16; off; off >>= 1)
        acc += __shfl_down_sync(0xffffffffu, acc, off);
    if ((r & 31) == 0) red[r >> 5] = acc;
    __syncthreads();
    if (r == 0) out[b * OO + o] = red[0] + red[1];
}

// ---------------------------------------------------------------------------
extern "C" void kernel_launch(void* const* d_in, const int* in_sizes, int n_in,
                              void* d_out, int out_size)
{
    const float* x = nullptr;
    const float* cores = nullptr;
    const float* oc = nullptr;
    for (int i = 0; i < n_in; i++) {
        if (in_sizes[i] == BB * SS * 2)              x = (const float*)d_in[i];
        else if (in_sizes[i] == SS * 64 * 64 * 2)    cores = (const float*)d_in[i];
        else if (in_sizes[i] == OO * 64 * 64)        oc = (const float*)d_in[i];
    }

    const int DYN_SMEM = RING * ESLAB_B + 1152 + 1568 + 64;
    cudaFuncSetAttribute(chain_kernel, cudaFuncAttributeMaxDynamicSharedMemorySize, DYN_SMEM);

    prepL_kernel<<<HALFS, 256>>>(cores);
    prepR_kernel<<<HALFS, 256>>>(cores);
    chain_kernel<<<64, NT, DYN_SMEM>>>(x);
    out_kernel<<<BB * OO, 64>>>(oc, (float*)d_out);
}

// round 14
// speedup vs baseline: 1.2480x; 1.0569x over previous
#include <cuda_runtime.h>
#include <cuda_fp16.h>
#include <cstdint>

#define BB 64
#define SS 196
#define HALFS 98
#define OO 10
#define ESLAB_U2 2048          // uint2 per E-slab: [mm 0..31][n 0..63]
#define ESLAB_B 16384          // bytes per E-slab
#define RING 6
#define NT 160                 // 4 worker warps + 1 TMA warp

// E = C - I in fp16, chain-ordered. uint2 = {half2 @ m=2mm, half2 @ m=2mm+1}
__device__ __align__(128) uint2 g_EhL[HALFS * ESLAB_U2];
__device__ __align__(128) uint2 g_EhR[HALFS * ESLAB_U2];   // transposed
__device__ float g_vecL[BB][64];
__device__ float g_vecR[BB][64];

// ---------------------------------------------------------------------------
__device__ __forceinline__ uint32_t smem_u32(const void* p) {
    uint32_t a;
    asm("{ .reg .u64 t; cvta.to.shared.u64 t, %1; cvt.u32.u64 %0, t; }"
        : "=r"(a) : "l"(p));
    return a;
}
__device__ __forceinline__ void mbar_init(uint32_t a, uint32_t cnt) {
    asm volatile("mbarrier.init.shared.b64 [%0], %1;" :: "r"(a), "r"(cnt) : "memory");
}
__device__ __forceinline__ void mbar_expect_tx(uint32_t a, uint32_t bytes) {
    asm volatile("mbarrier.arrive.expect_tx.shared.b64 _, [%0], %1;"
                 :: "r"(a), "r"(bytes) : "memory");
}
__device__ __forceinline__ void mbar_wait(uint32_t a, uint32_t phase) {
    asm volatile(
        "{\n\t.reg .pred P;\n\t"
        "W_%=:\n\t"
        "mbarrier.try_wait.parity.shared.b64 P, [%0], %1;\n\t"
        "@!P bra W_%=;\n\t}"
        :: "r"(a), "r"(phase) : "memory");
}
__device__ __forceinline__ void bulk_g2s(uint32_t dst, const void* src,
                                         uint32_t bytes, uint32_t mbar) {
    asm volatile(
        "cp.async.bulk.shared::cluster.global.mbarrier::complete_tx::bytes "
        "[%0], [%1], %2, [%3];"
        :: "r"(dst), "l"(src), "r"(bytes), "r"(mbar) : "memory");
}

__device__ __forceinline__ uint32_t pack_e(float2 a) {
    __half2 h = __float22half2_rn(a);
    uint32_t u;
    memcpy(&u, &h, 4);
    return u;
}

// ---------------------------------------------------------------------------
// Kernel 1a: left prep (direct, coalesced). CTA = slab s.
// ---------------------------------------------------------------------------
__global__ __launch_bounds__(256) void prepL_kernel(const float* __restrict__ cores)
{
    const int s = blockIdx.x;
    const int t = threadIdx.x;
    const float2* c2 = (const float2*)cores + (size_t)s * 4096;
    uint2* dst = g_EhL + (size_t)s * ESLAB_U2;

#pragma unroll
    for (int i = 0; i < 8; i++) {
        int idx = t + i * 256;
        int mm = idx >> 6, n = idx & 63;
        float2 a = c2[(2 * mm) * 64 + n];
        float2 b = c2[(2 * mm + 1) * 64 + n];
        if (2 * mm == n)     { a.x -= 1.f; a.y -= 1.f; }
        if (2 * mm + 1 == n) { b.x -= 1.f; b.y -= 1.f; }
        dst[idx] = make_uint2(pack_e(a), pack_e(b));
    }
}

// ---------------------------------------------------------------------------
// Kernel 1b: right prep (transpose via SMEM tile). CTA = chain index k.
// ---------------------------------------------------------------------------
__global__ __launch_bounds__(256) void prepR_kernel(const float* __restrict__ cores)
{
    __shared__ uint2 tile[32][65];
    const int k = blockIdx.x;
    const int s = SS - 1 - k;
    const float4* c4 = (const float4*)cores + (size_t)s * 2048;  // [n][mm] float4
    uint2* dst = g_EhR + (size_t)k * ESLAB_U2;
    const int t = threadIdx.x;

#pragma unroll
    for (int i = 0; i < 8; i++) {
        int idx = t + i * 256;                 // mm fastest -> coalesced float4
        int n = idx >> 5, mm = idx & 31;
        float4 f = c4[idx];
        float2 a = make_float2(f.x, f.y);
        float2 b = make_float2(f.z, f.w);
        if (2 * mm == n)     { a.x -= 1.f; a.y -= 1.f; }
        if (2 * mm + 1 == n) { b.x -= 1.f; b.y -= 1.f; }
        tile[mm][n] = make_uint2(pack_e(a), pack_e(b));
    }
    __syncthreads();
#pragma unroll
    for (int i = 0; i < 8; i++) {
        int idx = t + i * 256;                 // n fastest -> coalesced store
        int mm = idx >> 6, n = idx & 63;
        dst[idx] = tile[mm][n];
    }
}

// ---------------------------------------------------------------------------
// Kernel 2: 128 CTAs x 160 threads — ONE chain per CTA (batch b, half).
// Worker warp w, lane (g = m-half, c): column n = w*16 + c.
// fp16-E staging via TMA ring; prefetch converts in the post-STS window.
// Identity term exact in fp32. One __syncthreads per step.
// ---------------------------------------------------------------------------
__global__ __launch_bounds__(NT, 1) void chain_kernel(const float* __restrict__ x)
{
    extern __shared__ __align__(128) unsigned char dynsm[];
    uint2*  ringE = (uint2*)dynsm;                                // 6 x 16KB
    float*  lvsm  = (float*)(dynsm + RING * ESLAB_B);             // [2][72]
    float2* xsh   = (float2*)(dynsm + RING * ESLAB_B + 576);      // [98]
    uint64_t* mbp = (uint64_t*)(dynsm + RING * ESLAB_B + 576 + 784);

    const uint32_t fb = smem_u32(mbp);
    const uint32_t ru = smem_u32(dynsm);

    const int t    = threadIdx.x;
    const int w    = t >> 5;
    const int lane = t & 31;
    const int g    = lane >> 4;
    const int half = blockIdx.x >> 6;
    const int b    = blockIdx.x & 63;

    const uint2* srcE = half ? g_EhR : g_EhL;     // both chain-ordered

    // stage x in iteration order
    const float2* xf = (const float2*)x;          // [B][S]
    for (int k = t; k < HALFS; k += NT) {
        int s = half ? (SS - 1 - k) : k;
        xsh[k] = xf[b * SS + s];
    }
    // init lv buf0 (padded layout: half h at offset h*36)
    if (t < 64) {
        int h = t >> 5, p = t & 31;
        lvsm[h * 36 + p] = (t == 0) ? 1.f : 0.f;
    }
    if (t == 0)
        for (int j = 0; j < RING; j++) mbar_init(fb + 8 * j, 1);
    __syncthreads();

    if (w == 4 && lane == 0) {            // prologue: slabs 0..5
        for (int s = 0; s < RING; s++) {
            mbar_expect_tx(fb + 8 * s, ESLAB_B);
            bulk_g2s(ru + s * ESLAB_B, srcE + (size_t)s * ESLAB_U2,
                     ESLAB_B, fb + 8 * s);
        }
        mbar_wait(fb + 0, 0);             // slab 0 (reg load)
        mbar_wait(fb + 8, 0);             // slab 1 (step-0 prefetch)
    }
    __syncthreads();

    if (w < 4) {
        // ============================ workers ============================
        const int c  = lane & 15;
        const int n  = w * 16 + c;
        const int eoff = g * 1024 + n;    // uint2 offset of (mm = g*16, n)
        const int hh = w >> 1;            // n >> 5
        const int sto = hh * 36 + (w & 1) * 16 + c;   // lv slot for column n
        const bool wr = (g == 0);

        float2 A[32], B[32];
        {
            const uint2* P = ringE + eoff;
#pragma unroll
            for (int j = 0; j < 16; j++) {
                uint2 e = P[j * 64];
                A[2 * j]     = __half22float2(*reinterpret_cast<const __half2*>(&e.x));
                A[2 * j + 1] = __half22float2(*reinterpret_cast<const __half2*>(&e.y));
            }
        }
        int slotn = 1;                    // ring slot of slab k+1

#define WSTEP(CUR, NXT, K, PAR)                                              \
        {                                                                    \
            float2 xk = xsh[(K)];                                            \
            float p0;                                                        \
            {                                                                \
                const float4* lv4 = (const float4*)(lvsm + (PAR) * 72 + g * 36); \
                float4 L[8];                                                 \
                _Pragma("unroll")                                            \
                for (int q = 0; q < 8; q++) L[q] = lv4[q];                   \
                float sx0 = 0.f, sx1 = 0.f, sy0 = 0.f, sy1 = 0.f;            \
                _Pragma("unroll")                                            \
                for (int q = 0; q < 8; q++) {                                \
                    float2 c0 = CUR[4*q+0], c1 = CUR[4*q+1];                 \
                    float2 c2 = CUR[4*q+2], c3 = CUR[4*q+3];                 \
                    sx0 = fmaf(L[q].x, c0.x, sx0); sy0 = fmaf(L[q].x, c0.y, sy0); \
                    sx1 = fmaf(L[q].y, c1.x, sx1); sy1 = fmaf(L[q].y, c1.y, sy1); \
                    sx0 = fmaf(L[q].z, c2.x, sx0); sy0 = fmaf(L[q].z, c2.y, sy0); \
                    sx1 = fmaf(L[q].w, c3.x, sx1); sy1 = fmaf(L[q].w, c3.y, sy1); \
                }                                                            \
                p0 = fmaf(xk.x, sx0 + sx1, xk.y * (sy0 + sy1));              \
            }                                                                \
            float lvo = 0.f;                                                 \
            if (wr) lvo = lvsm[(PAR) * 72 + sto];                            \
            float oth = __shfl_xor_sync(0xffffffffu, p0, 16);                \
            if (wr) lvsm[((PAR) ^ 1) * 72 + sto] =                           \
                fmaf(xk.x + xk.y, lvo, p0 + oth);                            \
            /* ------ prefetch+convert slab K+1 (post-STS skew window) --- */\
            if ((K) < HALFS - 1) {                                           \
                const uint2* Ns = ringE + slotn * ESLAB_U2 + eoff;           \
                _Pragma("unroll")                                            \
                for (int j = 0; j < 16; j++) {                               \
                    uint2 e = Ns[j * 64];                                    \
                    NXT[2 * j] =                                             \
                        __half22float2(*reinterpret_cast<const __half2*>(&e.x)); \
                    NXT[2 * j + 1] =                                         \
                        __half22float2(*reinterpret_cast<const __half2*>(&e.y)); \
                }                                                            \
            }                                                                \
            slotn = (slotn == RING - 1) ? 0 : slotn + 1;                     \
            __syncthreads();                                                 \
        }

#pragma unroll 1
        for (int k = 0; k < HALFS; k += 2) {
            WSTEP(A, B, k, 0);
            WSTEP(B, A, k + 1, 1);
        }
#undef WSTEP

        if (t < 64) {        // final lv in buffer 0 (98 even)
            int h = t >> 5, p = t & 31;
            float v = lvsm[h * 36 + p];
            if (half == 0) g_vecL[b][t] = v;
            else           g_vecR[b][t] = v;
        }
    } else {
        // ============================ TMA warp ============================
#pragma unroll 1
        for (int k = 0; k < HALFS; k++) {
            if (lane == 0 && k + 2 < HALFS)     // certify slab k+2
                mbar_wait(fb + 8 * ((k + 2) % RING), ((k + 2) / RING) & 1);
            __syncthreads();
            if (lane == 0 && k + RING < HALFS) {   // refill slot k%RING
                mbar_expect_tx(fb + 8 * (k % RING), ESLAB_B);
                bulk_g2s(ru + (k % RING) * ESLAB_B,
                         srcE + (size_t)(k + RING) * ESLAB_U2,
                         ESLAB_B, fb + 8 * (k % RING));
            }
        }
    }
}

// ---------------------------------------------------------------------------
// Kernel 3: 64 CTAs (one per b) x 320 threads (warp = o).
// Lane covers columns {lane, lane+32}: colsum_r = sum_l L[l]*oc[o][l][r],
// acc = colsum0*R[r0] + colsum1*R[r1], warp-reduce, lane0 writes.
// ---------------------------------------------------------------------------
__global__ __launch_bounds__(320) void out_kernel(const float* __restrict__ oc,
                                                  float* __restrict__ out)
{
    const int b    = blockIdx.x;
    const int t    = threadIdx.x;
    const int o    = t >> 5;
    const int lane = t & 31;
    __shared__ float Ls[64];
    __shared__ float Rs[64];

    if (t < 64)  Ls[t] = g_vecL[b][t];
    else if (t < 128) Rs[t - 64] = g_vecR[b][t - 64];
    __syncthreads();

    const float r0 = Rs[lane], r1 = Rs[lane + 32];
    const float* base = oc + o * 4096 + lane;
    float c0 = 0.f, c1 = 0.f;
#pragma unroll
    for (int l = 0; l < 64; l++) {
        float Ll = Ls[l];
        c0 = fmaf(Ll, base[l * 64], c0);
        c1 = fmaf(Ll, base[l * 64 + 32], c1);
    }
    float acc = fmaf(c0, r0, c1 * r1);
#pragma unroll
    for (int off = 16; off; off >>= 1)
        acc += __shfl_down_sync(0xffffffffu, acc, off);
    if (lane == 0) out[b * OO + o] = acc;
}

// ---------------------------------------------------------------------------
extern "C" void kernel_launch(void* const* d_in, const int* in_sizes, int n_in,
                              void* d_out, int out_size)
{
    const float* x = nullptr;
    const float* cores = nullptr;
    const float* oc = nullptr;
    for (int i = 0; i < n_in; i++) {
        if (in_sizes[i] == BB * SS * 2)              x = (const float*)d_in[i];
        else if (in_sizes[i] == SS * 64 * 64 * 2)    cores = (const float*)d_in[i];
        else if (in_sizes[i] == OO * 64 * 64)        oc = (const float*)d_in[i];
    }

    const int DYN_SMEM = RING * ESLAB_B + 576 + 784 + 64;
    cudaFuncSetAttribute(chain_kernel, cudaFuncAttributeMaxDynamicSharedMemorySize, DYN_SMEM);

    prepL_kernel<<<HALFS, 256>>>(cores);
    prepR_kernel<<<HALFS, 256>>>(cores);
    chain_kernel<<<128, NT, DYN_SMEM>>>(x);
    out_kernel<<<BB, 320>>>(oc, (float*)d_out);
}

// round 15
// speedup vs baseline: 1.3199x; 1.0576x over previous
#include <cuda_runtime.h>
#include <cuda_fp16.h>
#include <cstdint>

#define BB 64
#define SS 196
#define HALFS 98
#define OO 10
#define ESLAB_U2 2048          // uint2 per E-slab: [mm 0..31][n 0..63]
#define ESLAB_B 16384          // bytes per E-slab
#define RING 6
#define NT 160                 // 4 worker warps + 1 TMA warp

// E = C - I in fp16, chain-ordered. uint2 = {half2 @ m=2mm, half2 @ m=2mm+1}
__device__ __align__(128) uint2 g_EhL[HALFS * ESLAB_U2];
__device__ __align__(128) uint2 g_EhR[HALFS * ESLAB_U2];   // transposed
__device__ float g_vecL[BB][64];
__device__ float g_vecR[BB][64];

// ---------------------------------------------------------------------------
__device__ __forceinline__ uint32_t smem_u32(const void* p) {
    uint32_t a;
    asm("{ .reg .u64 t; cvta.to.shared.u64 t, %1; cvt.u32.u64 %0, t; }"
        : "=r"(a) : "l"(p));
    return a;
}
__device__ __forceinline__ void mbar_init(uint32_t a, uint32_t cnt) {
    asm volatile("mbarrier.init.shared.b64 [%0], %1;" :: "r"(a), "r"(cnt) : "memory");
}
__device__ __forceinline__ void mbar_expect_tx(uint32_t a, uint32_t bytes) {
    asm volatile("mbarrier.arrive.expect_tx.shared.b64 _, [%0], %1;"
                 :: "r"(a), "r"(bytes) : "memory");
}
__device__ __forceinline__ void mbar_wait(uint32_t a, uint32_t phase) {
    asm volatile(
        "{\n\t.reg .pred P;\n\t"
        "W_%=:\n\t"
        "mbarrier.try_wait.parity.shared.b64 P, [%0], %1;\n\t"
        "@!P bra W_%=;\n\t}"
        :: "r"(a), "r"(phase) : "memory");
}
__device__ __forceinline__ void bulk_g2s(uint32_t dst, const void* src,
                                         uint32_t bytes, uint32_t mbar) {
    asm volatile(
        "cp.async.bulk.shared::cluster.global.mbarrier::complete_tx::bytes "
        "[%0], [%1], %2, [%3];"
        :: "r"(dst), "l"(src), "r"(bytes), "r"(mbar) : "memory");
}

__device__ __forceinline__ uint32_t pack_e(float2 a) {
    __half2 h = __float22half2_rn(a);
    uint32_t u;
    memcpy(&u, &h, 4);
    return u;
}

// ---------------------------------------------------------------------------
// Kernel 1a: left prep (direct, coalesced). CTA = slab s.
// ---------------------------------------------------------------------------
__global__ __launch_bounds__(256) void prepL_kernel(const float* __restrict__ cores)
{
    const int s = blockIdx.x;
    const int t = threadIdx.x;
    const float2* c2 = (const float2*)cores + (size_t)s * 4096;
    uint2* dst = g_EhL + (size_t)s * ESLAB_U2;

#pragma unroll
    for (int i = 0; i < 8; i++) {
        int idx = t + i * 256;
        int mm = idx >> 6, n = idx & 63;
        float2 a = c2[(2 * mm) * 64 + n];
        float2 b = c2[(2 * mm + 1) * 64 + n];
        if (2 * mm == n)     { a.x -= 1.f; a.y -= 1.f; }
        if (2 * mm + 1 == n) { b.x -= 1.f; b.y -= 1.f; }
        dst[idx] = make_uint2(pack_e(a), pack_e(b));
    }
}

// ---------------------------------------------------------------------------
// Kernel 1b: right prep (transpose via SMEM tile). CTA = chain index k.
// ---------------------------------------------------------------------------
__global__ __launch_bounds__(256) void prepR_kernel(const float* __restrict__ cores)
{
    __shared__ uint2 tile[32][65];
    const int k = blockIdx.x;
    const int s = SS - 1 - k;
    const float4* c4 = (const float4*)cores + (size_t)s * 2048;  // [n][mm] float4
    uint2* dst = g_EhR + (size_t)k * ESLAB_U2;
    const int t = threadIdx.x;

#pragma unroll
    for (int i = 0; i < 8; i++) {
        int idx = t + i * 256;                 // mm fastest -> coalesced float4
        int n = idx >> 5, mm = idx & 31;
        float4 f = c4[idx];
        float2 a = make_float2(f.x, f.y);
        float2 b = make_float2(f.z, f.w);
        if (2 * mm == n)     { a.x -= 1.f; a.y -= 1.f; }
        if (2 * mm + 1 == n) { b.x -= 1.f; b.y -= 1.f; }
        tile[mm][n] = make_uint2(pack_e(a), pack_e(b));
    }
    __syncthreads();
#pragma unroll
    for (int i = 0; i < 8; i++) {
        int idx = t + i * 256;                 // n fastest -> coalesced store
        int mm = idx >> 6, n = idx & 63;
        dst[idx] = tile[mm][n];
    }
}

// ---------------------------------------------------------------------------
// Kernel 2: 128 CTAs x 160 threads — ONE chain per CTA (batch b, half).
// Worker warp w, lane (g = m-half, c): column n = w*16 + c.
// fp16-E staging via TMA ring; prefetch converts in the post-STS window.
// Identity term exact in fp32. One __syncthreads per step.
// ---------------------------------------------------------------------------
__global__ __launch_bounds__(NT, 1) void chain_kernel(const float* __restrict__ x)
{
    extern __shared__ __align__(128) unsigned char dynsm[];
    uint2*  ringE = (uint2*)dynsm;                                // 6 x 16KB
    float*  lvsm  = (float*)(dynsm + RING * ESLAB_B);             // [2][72]
    float2* xsh   = (float2*)(dynsm + RING * ESLAB_B + 576);      // [98]
    uint64_t* mbp = (uint64_t*)(dynsm + RING * ESLAB_B + 576 + 784);

    const uint32_t fb = smem_u32(mbp);
    const uint32_t ru = smem_u32(dynsm);

    const int t    = threadIdx.x;
    const int w    = t >> 5;
    const int lane = t & 31;
    const int g    = lane >> 4;
    const int half = blockIdx.x >> 6;
    const int b    = blockIdx.x & 63;

    const uint2* srcE = half ? g_EhR : g_EhL;     // both chain-ordered

    // stage x in iteration order
    const float2* xf = (const float2*)x;          // [B][S]
    for (int k = t; k < HALFS; k += NT) {
        int s = half ? (SS - 1 - k) : k;
        xsh[k] = xf[b * SS + s];
    }
    // init lv buf0 (padded layout: half h at offset h*36)
    if (t < 64) {
        int h = t >> 5, p = t & 31;
        lvsm[h * 36 + p] = (t == 0) ? 1.f : 0.f;
    }
    if (t == 0)
        for (int j = 0; j < RING; j++) mbar_init(fb + 8 * j, 1);
    __syncthreads();

    if (w == 4 && lane == 0) {            // prologue: slabs 0..5
        for (int s = 0; s < RING; s++) {
            mbar_expect_tx(fb + 8 * s, ESLAB_B);
            bulk_g2s(ru + s * ESLAB_B, srcE + (size_t)s * ESLAB_U2,
                     ESLAB_B, fb + 8 * s);
        }
        mbar_wait(fb + 0, 0);             // slab 0 (reg load)
        mbar_wait(fb + 8, 0);             // slab 1 (step-0 prefetch)
    }
    __syncthreads();

    if (w < 4) {
        // ============================ workers ============================
        const int c  = lane & 15;
        const int n  = w * 16 + c;
        const int eoff = g * 1024 + n;    // uint2 offset of (mm = g*16, n)
        const int hh = w >> 1;            // n >> 5
        const int sto = hh * 36 + (w & 1) * 16 + c;   // lv slot for column n
        const bool wr = (g == 0);

        float2 A[32], B[32];
        {
            const uint2* P = ringE + eoff;
#pragma unroll
            for (int j = 0; j < 16; j++) {
                uint2 e = P[j * 64];
                A[2 * j]     = __half22float2(*reinterpret_cast<const __half2*>(&e.x));
                A[2 * j + 1] = __half22float2(*reinterpret_cast<const __half2*>(&e.y));
            }
        }
        int slotn = 1;                    // ring slot of slab k+1

#define WSTEP(CUR, NXT, K, PAR)                                              \
        {                                                                    \
            float2 xk = xsh[(K)];                                            \
            float p0;                                                        \
            {                                                                \
                const float4* lv4 = (const float4*)(lvsm + (PAR) * 72 + g * 36); \
                float4 L[8];                                                 \
                _Pragma("unroll")                                            \
                for (int q = 0; q < 8; q++) L[q] = lv4[q];                   \
                float sx0 = 0.f, sx1 = 0.f, sy0 = 0.f, sy1 = 0.f;            \
                _Pragma("unroll")                                            \
                for (int q = 0; q < 8; q++) {                                \
                    float2 c0 = CUR[4*q+0], c1 = CUR[4*q+1];                 \
                    float2 c2 = CUR[4*q+2], c3 = CUR[4*q+3];                 \
                    sx0 = fmaf(L[q].x, c0.x, sx0); sy0 = fmaf(L[q].x, c0.y, sy0); \
                    sx1 = fmaf(L[q].y, c1.x, sx1); sy1 = fmaf(L[q].y, c1.y, sy1); \
                    sx0 = fmaf(L[q].z, c2.x, sx0); sy0 = fmaf(L[q].z, c2.y, sy0); \
                    sx1 = fmaf(L[q].w, c3.x, sx1); sy1 = fmaf(L[q].w, c3.y, sy1); \
                }                                                            \
                p0 = fmaf(xk.x, sx0 + sx1, xk.y * (sy0 + sy1));              \
            }                                                                \
            float lvo = 0.f;                                                 \
            if (wr) lvo = lvsm[(PAR) * 72 + sto];                            \
            float oth = __shfl_xor_sync(0xffffffffu, p0, 16);                \
            if (wr) lvsm[((PAR) ^ 1) * 72 + sto] =                           \
                fmaf(xk.x + xk.y, lvo, p0 + oth);                            \
            /* ------ prefetch+convert slab K+1 (post-STS skew window) --- */\
            if ((K) < HALFS - 1) {                                           \
                const uint2* Ns = ringE + slotn * ESLAB_U2 + eoff;           \
                _Pragma("unroll")                                            \
                for (int j = 0; j < 16; j++) {                               \
                    uint2 e = Ns[j * 64];                                    \
                    NXT[2 * j] =                                             \
                        __half22float2(*reinterpret_cast<const __half2*>(&e.x)); \
                    NXT[2 * j + 1] =                                         \
                        __half22float2(*reinterpret_cast<const __half2*>(&e.y)); \
                }                                                            \
            }                                                                \
            slotn = (slotn == RING - 1) ? 0 : slotn + 1;                     \
            __syncthreads();                                                 \
        }

#pragma unroll 1
        for (int k = 0; k < HALFS; k += 2) {
            WSTEP(A, B, k, 0);
            WSTEP(B, A, k + 1, 1);
        }
#undef WSTEP

        if (t < 64) {        // final lv in buffer 0 (98 even)
            int h = t >> 5, p = t & 31;
            float v = lvsm[h * 36 + p];
            if (half == 0) g_vecL[b][t] = v;
            else           g_vecR[b][t] = v;
        }
    } else {
        // ============================ TMA warp ============================
#pragma unroll 1
        for (int k = 0; k < HALFS; k++) {
            if (lane == 0 && k + 2 < HALFS)     // certify slab k+2
                mbar_wait(fb + 8 * ((k + 2) % RING), ((k + 2) / RING) & 1);
            __syncthreads();
            if (lane == 0 && k + RING < HALFS) {   // refill slot k%RING
                mbar_expect_tx(fb + 8 * (k % RING), ESLAB_B);
                bulk_g2s(ru + (k % RING) * ESLAB_B,
                         srcE + (size_t)(k + RING) * ESLAB_U2,
                         ESLAB_B, fb + 8 * (k % RING));
            }
        }
    }
}

// ---------------------------------------------------------------------------
// Kernel 3: 640 CTAs (b,o) x 256 threads, coalesced float4 streaming.
// Thread t dots 4 linear float4 chunks of oc[o] against R quadruples,
// scales by Ls[l], block-reduces 256 -> 1.
// ---------------------------------------------------------------------------
__global__ __launch_bounds__(256) void out_kernel(const float* __restrict__ oc,
                                                  float* __restrict__ out)
{
    const int b = blockIdx.x / OO;
    const int o = blockIdx.x - b * OO;
    const int t = threadIdx.x;
    __shared__ float Ls[64];
    __shared__ float Rs[64];
    __shared__ float red[8];

    if (t < 64)       Ls[t] = g_vecL[b][t];
    else if (t < 128) Rs[t - 64] = g_vecR[b][t - 64];
    __syncthreads();

    const float4* oc4 = (const float4*)(oc + (size_t)o * 4096);
    float acc = 0.f;
#pragma unroll
    for (int j = 0; j < 4; j++) {
        int idx = t + 256 * j;                 // float4 index in [0,1024)
        float4 a = oc4[idx];                   // coalesced LDG.128
        const float4 r = *(const float4*)(Rs + (idx & 15) * 4);
        float d = fmaf(a.x, r.x, fmaf(a.y, r.y, fmaf(a.z, r.z, a.w * r.w)));
        acc = fmaf(Ls[idx >> 4], d, acc);
    }
#pragma unroll
    for (int off = 16; off; off >>= 1)
        acc += __shfl_down_sync(0xffffffffu, acc, off);
    if ((t & 31) == 0) red[t >> 5] = acc;
    __syncthreads();
    if (t < 8) {
        float v = red[t];
        v += __shfl_down_sync(0xffu, v, 4);
        v += __shfl_down_sync(0xffu, v, 2);
        v += __shfl_down_sync(0xffu, v, 1);
        if (t == 0) out[b * OO + o] = v;
    }
}

// ---------------------------------------------------------------------------
extern "C" void kernel_launch(void* const* d_in, const int* in_sizes, int n_in,
                              void* d_out, int out_size)
{
    const float* x = nullptr;
    const float* cores = nullptr;
    const float* oc = nullptr;
    for (int i = 0; i < n_in; i++) {
        if (in_sizes[i] == BB * SS * 2)              x = (const float*)d_in[i];
        else if (in_sizes[i] == SS * 64 * 64 * 2)    cores = (const float*)d_in[i];
        else if (in_sizes[i] == OO * 64 * 64)        oc = (const float*)d_in[i];
    }

    const int DYN_SMEM = RING * ESLAB_B + 576 + 784 + 64;
    cudaFuncSetAttribute(chain_kernel, cudaFuncAttributeMaxDynamicSharedMemorySize, DYN_SMEM);

    prepL_kernel<<<HALFS, 256>>>(cores);
    prepR_kernel<<<HALFS, 256>>>(cores);
    chain_kernel<<<128, NT, DYN_SMEM>>>(x);
    out_kernel<<<BB * OO, 256>>>(oc, (float*)d_out);
}